// round 16
// baseline (speedup 1.0000x reference)
#include <cuda_runtime.h>
#include <cuda_fp16.h>
#include <math.h>
#include <stdint.h>

// ---------------------------------------------------------------------------
// Problem constants
// ---------------------------------------------------------------------------
static constexpr int BATCH = 256;
static constexpr int SEQ   = 128;
static constexpr int HID   = 512;
static constexpr int G4    = 2048;
static constexpr int BB    = 768;

static constexpr int NCTA   = 128;
static constexpr int M_TILE = 192;
// Fused layer smem: Wh slice + Wx slice + c + bias
static constexpr int SMF_BYTES = (16384 + 16384 + M_TILE * 16 + 64) * 4;  // 143616
// Plain layer smem: Wh slice + c
static constexpr int SMP_BYTES = (16384 + M_TILE * 16) * 4;               // 77824

// gemm_x (layer 0)
static constexpr int XA_KGW = 128 * 8 + 8;
static constexpr int X_B = 0;
static constexpr int X_A = 16384;
static constexpr int X_WORDS = X_A + 2 * 4 * XA_KGW;
static constexpr int X_BYTES = X_WORDS * 4;

// ---------------------------------------------------------------------------
// Scratch (device globals; no runtime allocation allowed)
// ---------------------------------------------------------------------------
__device__ uint32_t g_seqH[(size_t)BB * SEQ * 256];     // permuted fp16 embeddings
__device__ uint32_t g_gxA [(size_t)BB * SEQ * G4 / 2];  // fp16 gx ping (frag layout)
__device__ uint32_t g_gxB [(size_t)BB * SEQ * G4 / 2];  // fp16 gx pong
__device__ uint32_t g_hPa [(size_t)BB * 256];           // permuted fp16 h ping
__device__ uint32_t g_hPb [(size_t)BB * 256];           // permuted fp16 h pong
__device__ float    g_hf  [(size_t)BB * HID];           // exact fp32 final h
__device__ uint32_t g_WxP [(size_t)3 * 32 * 16384];     // packed fp16 Wx slices
__device__ uint32_t g_WhP [(size_t)3 * 32 * 16384];     // packed fp16 Wh slices
__device__ float    g_bp  [3 * G4];
__device__ float    g_xn1 [BATCH * 1536];
__device__ float    g_a1  [BATCH * 1024];
__device__ float    g_xn2 [BATCH * 1024];
__device__ float    g_W2p [1024 * 128];
__device__ float    g_b2p [128];
__device__ float    g_a2  [BATCH * 128];
__device__ float    g_a2n [BATCH * 128];

// Grid barrier state (monotonic phase; graph-replay safe)
__device__ unsigned int g_bar_count;
__device__ unsigned int g_bar_phase;

// ---------------------------------------------------------------------------
// Helpers
// ---------------------------------------------------------------------------
__device__ __forceinline__ void mma16(float* c, const uint32_t* a, const uint32_t* b) {
    asm volatile(
        "mma.sync.aligned.m16n8k16.row.col.f32.f16.f16.f32 "
        "{%0,%1,%2,%3}, {%4,%5,%6,%7}, {%8,%9}, {%0,%1,%2,%3};"
        : "+f"(c[0]), "+f"(c[1]), "+f"(c[2]), "+f"(c[3])
        : "r"(a[0]), "r"(a[1]), "r"(a[2]), "r"(a[3]), "r"(b[0]), "r"(b[1]));
}

__device__ __forceinline__ unsigned int ld_acq(const unsigned int* p) {
    unsigned int v;
    asm volatile("ld.acquire.gpu.u32 %0, [%1];" : "=r"(v) : "l"(p));
    return v;
}

__device__ __forceinline__ float fsig(float x) {
    return __fdividef(1.f, 1.f + __expf(-x));
}
__device__ __forceinline__ float ftanh(float x) {
    return __fdividef(2.f, 1.f + __expf(-2.f * x)) - 1.f;
}

__device__ __forceinline__ int kperm_word(int u) {        // u even; word index
    int j = (u >> 1) & 7;
    return (u >> 4) * 8 + (j & 3) * 2 + (j >> 2);
}

// N-side gate-to-column mapping (shfl-free epilogue).
__device__ __forceinline__ int gate_col(int u_loc, int g) {
    int wni = u_loc >> 3, u7 = u_loc & 7;
    int nfp = u7 >> 2, qq = u7 & 3;
    return wni * 32 + (nfp * 2 + (g >> 1)) * 8 + qq * 2 + (g & 1);
}

// ---------------------------------------------------------------------------
// gx fragment-native mapping, fp16 (consumer: 8 warps, warp tile 48x32).
// ---------------------------------------------------------------------------
__device__ __forceinline__ void store_gx_frag_h(uint32_t* gxL, int r, int n, float2 v) {
    int t   = r & 127, bb = r >> 7;
    int mb  = bb / 192, rl = bb - mb * 192;
    int wmi = rl / 48,  rlp = rl - wmi * 48;
    int mfl = rlp >> 4, pp = rlp & 15;
    int nb  = n >> 6,   ncl = n & 63;
    int wni = ncl >> 5, ncl2 = ncl & 31;
    int nfl = ncl2 >> 3, ql = (ncl2 & 7) >> 1;
    size_t idx = ((((size_t)t * 128 + mb * 32 + nb) * 8 + wmi * 2 + wni) * 32
                  + (pp & 7) * 4 + ql) * 24 + (mfl * 4 + nfl) * 2 + (pp >> 3);
    __half2 h = __floats2half2_rn(v.x, v.y);
    gxL[idx] = *(uint32_t*)&h;
}

// ---------------------------------------------------------------------------
// Embedding gather -> permuted fp16
// ---------------------------------------------------------------------------
__global__ void embed_kernel(const int* __restrict__ t1, const int* __restrict__ t2,
                             const int* __restrict__ t3, const float* __restrict__ emb,
                             __half2* __restrict__ out) {
    int bbt = blockIdx.x;
    int bb  = bbt >> 7;
    int t   = bbt & 127;
    int s   = bb >> 8;
    int b   = bb & 255;
    const int* txt = (s == 0) ? t1 : (s == 1 ? t2 : t3);
    int tok = txt[b * SEQ + t];
    int u0  = threadIdx.x * 4;
    float4 v = *(const float4*)(emb + (size_t)tok * HID + u0);
    __half2* dst = out + (size_t)bbt * 256;
    dst[kperm_word(u0)]     = __floats2half2_rn(v.x, v.y);
    dst[kperm_word(u0 + 2)] = __floats2half2_rn(v.z, v.w);
}

// ---------------------------------------------------------------------------
// Weight/bias permutation (gate_col N-mapping; packed k-perm format):
//   WxP/WhP [l][slice(32)][kg(32)][col(64)*8 + wpos]
// ---------------------------------------------------------------------------
__global__ void prep_kernel(const float* __restrict__ lw, const float* __restrict__ lb,
                            uint32_t* __restrict__ wxp, uint32_t* __restrict__ whp,
                            float* __restrict__ bp) {
    int idx = blockIdx.x * 256 + threadIdx.x;
    int l   = idx / (1024 * G4);
    int rem = idx - l * 1024 * G4;
    int k   = rem / G4;
    int n   = rem - k * G4;
    int u   = n >> 2, g = n & 3;
    float v = lw[(size_t)l * 1024 * G4 + (size_t)k * G4 + g * HID + u];
    __half hv = __float2half_rn(v);

    int s = u >> 4;
    int c = gate_col(u & 15, g);
    int kk = (k < HID) ? k : (k - HID);
    int kg = kk >> 4, j = (kk >> 1) & 7;
    int wpos = (j & 3) * 2 + (j >> 2);
    int half = kk & 1;
    size_t hidx = (((((size_t)l * 32 + s) * 32 + kg) * 512) + c * 8 + wpos) * 2 + half;
    if (k < HID) ((__half*)wxp)[hidx] = hv;
    else         ((__half*)whp)[hidx] = hv;

    if (idx < 3 * G4) {
        int ll = idx / G4, nn = idx - ll * G4;
        int uu = nn >> 2, gg = nn & 3;
        int ss = uu >> 4, cc = gate_col(uu & 15, gg);
        bp[ll * G4 + ss * 64 + cc] = lb[ll * G4 + gg * HID + uu];
    }
}

// ---------------------------------------------------------------------------
// Layer-0 x-GEMM (fp16 mma): gx = emb @ Wx0 + b0, fp16 fragment-native out.
// ---------------------------------------------------------------------------
__global__ void __launch_bounds__(256)
gemm_x_f16(const uint32_t* __restrict__ A, const uint32_t* __restrict__ BP,
           const float* __restrict__ bias, uint32_t* __restrict__ gxL) {
    extern __shared__ uint32_t xs[];
    uint32_t* Bs = xs + X_B;
    uint32_t* As = xs + X_A;

    const int tid  = threadIdx.x;
    const int lane = tid & 31, warp = tid >> 5;
    const int q    = lane & 3;
    const int p    = lane >> 2;
    const int wm   = (warp >> 1) * 32;
    const int wn   = (warp & 1) * 32;
    const int m0   = blockIdx.y * 128;
    const int n0   = blockIdx.x * 64;

    {
        const uint4* src = (const uint4*)(BP + (size_t)blockIdx.x * 16384);
        #pragma unroll
        for (int i = 0; i < 16; i++)
            *(uint4*)(Bs + (tid + i * 256) * 4) = src[tid + i * 256];
    }

    float acc[2][4][4] = {};

    uint4 v[4];
    {
        #pragma unroll
        for (int i = 0; i < 4; i++) {
            int idx = tid + i * 256;
            int row = idx >> 3, part = idx & 7;
            v[i] = *((const uint4*)A + (size_t)(m0 + row) * 64 + part);
        }
    }
    __syncthreads();

    #pragma unroll 1
    for (int ct = 0; ct <= 8; ct++) {
        __syncthreads();
        if (ct < 8) {
            uint32_t* Ab = As + (ct & 1) * (4 * XA_KGW);
            #pragma unroll
            for (int i = 0; i < 4; i++) {
                int idx = tid + i * 256;
                int row = idx >> 3, part = idx & 7;
                *(uint4*)(Ab + (part >> 1) * XA_KGW + row * 8 + (part & 1) * 4) = v[i];
            }
        }
        if (ct < 7) {
            #pragma unroll
            for (int i = 0; i < 4; i++) {
                int idx = tid + i * 256;
                int row = idx >> 3, part = idx & 7;
                v[i] = *((const uint4*)A + (size_t)(m0 + row) * 64 + (ct + 1) * 8 + part);
            }
        }
        if (ct >= 1) {
            const uint32_t* Ab2 = As + ((ct - 1) & 1) * (4 * XA_KGW);
            #pragma unroll
            for (int kgl = 0; kgl < 4; kgl++) {
                const int kg = (ct - 1) * 4 + kgl;
                uint32_t af[2][4];
                #pragma unroll
                for (int mf = 0; mf < 2; mf++) {
                    int rl = wm + mf * 16 + p;
                    uint2 p0 = *(const uint2*)&Ab2[kgl * XA_KGW + rl * 8 + q * 2];
                    uint2 p1 = *(const uint2*)&Ab2[kgl * XA_KGW + (rl + 8) * 8 + q * 2];
                    af[mf][0] = p0.x; af[mf][1] = p1.x;
                    af[mf][2] = p0.y; af[mf][3] = p1.y;
                }
                #pragma unroll
                for (int nf = 0; nf < 4; nf++) {
                    int nl = wn + nf * 8 + p;
                    uint2 pb = *(const uint2*)&Bs[kg * 512 + nl * 8 + q * 2];
                    uint32_t bf[2] = {pb.x, pb.y};
                    #pragma unroll
                    for (int mf = 0; mf < 2; mf++)
                        mma16(acc[mf][nf], af[mf], bf);
                }
            }
        }
    }

    #pragma unroll
    for (int mf = 0; mf < 2; mf++) {
        int r = m0 + wm + mf * 16 + p;
        #pragma unroll
        for (int nf = 0; nf < 4; nf++) {
            int n = n0 + wn + nf * 8 + 2 * q;
            float b0 = bias[n], b1 = bias[n + 1];
            float2 v0 = make_float2(acc[mf][nf][0] + b0, acc[mf][nf][1] + b1);
            float2 v1 = make_float2(acc[mf][nf][2] + b0, acc[mf][nf][3] + b1);
            store_gx_frag_h(gxL, r,     n, v0);
            store_gx_frag_h(gxL, r + 8, n, v1);
        }
    }
}

// ---------------------------------------------------------------------------
// Persistent LSTM layer, SPLIT-PHASE (R16):
//   phase 1: h-GEMM (Bh) + cell epilogue -> __syncthreads -> barrier ARRIVE
//   phase 2 (inside barrier window): x-GEMM (Bx, A re-loaded from hin which
//            stays valid all step) + batched gx store
//   phase 3: per-warp barrier WAIT (lane0 spin + __syncwarp)
// acc / accx never live together -> halved fp32 accumulator pressure.
// Identical mma sequences per output element -> bit-identical results.
// ---------------------------------------------------------------------------
template <bool FUSE_X, bool LAST>
__global__ void __launch_bounds__(256, 1)
lstm_layer(const uint32_t* __restrict__ WhS, const uint32_t* __restrict__ WxS,
           const uint32_t* __restrict__ gx, const float* __restrict__ bias_n,
           uint32_t* __restrict__ hA, uint32_t* __restrict__ hB,
           uint32_t* __restrict__ gx_out, float* __restrict__ h_final) {
    extern __shared__ uint32_t smem[];
    uint32_t* Bh    = smem;
    uint32_t* Bx    = smem + (FUSE_X ? 16384 : 0);
    float*    csm   = (float*)(smem + (FUSE_X ? 32768 : 16384));
    float*    biasx = csm + M_TILE * 16;

    const int tid  = threadIdx.x;
    const int lane = tid & 31, warp = tid >> 5;
    const int q    = lane & 3;
    const int p    = lane >> 2;
    const int wm   = (warp >> 1) * 48;
    const int wn   = (warp & 1) * 32;
    const int m0   = (blockIdx.x >> 5) * M_TILE;
    const int n0   = (blockIdx.x & 31) * 64;

    unsigned int phase = 0;
    if (lane == 0) phase = ld_acq(&g_bar_phase);

    // Resident B slices
    {
        const uint4* srcH = (const uint4*)(WhS + (size_t)(blockIdx.x & 31) * 16384);
        #pragma unroll
        for (int i = 0; i < 16; i++)
            *(uint4*)(Bh + (tid + i * 256) * 4) = srcH[tid + i * 256];
        if (FUSE_X) {
            const uint4* srcX = (const uint4*)(WxS + (size_t)(blockIdx.x & 31) * 16384);
            #pragma unroll
            for (int i = 0; i < 16; i++)
                *(uint4*)(Bx + (tid + i * 256) * 4) = srcX[tid + i * 256];
        }
    }
    if (FUSE_X && tid < 64) biasx[tid] = bias_n[n0 + tid];
    for (int i = tid; i < M_TILE * 16; i += 256) csm[i] = 0.f;
    __syncthreads();

    // Prefetch gx fragments for t = 0.
    uint32_t gxw[24];
    {
        const uint4* gp = (const uint4*)gx +
            ((((size_t)0 * 128 + blockIdx.x) * 8 + warp) * 32 + lane) * 6;
        #pragma unroll
        for (int j = 0; j < 6; j++) *(uint4*)(gxw + j * 4) = gp[j];
    }

    const int r0 = m0 + wm + p;

    const int tEnd = FUSE_X ? SEQ : SEQ - 1;
    for (int t = 0; t <= tEnd; t++) {
        const uint32_t* hin  = (t & 1) ? hB : hA;
        uint32_t*       hout = (t & 1) ? hA : hB;

        // ---------------- phase 1: h-GEMM + cell epilogue -------------------
        if (t < SEQ) {
            float acc[3][4][4] = {};
            if (t > 0) {
                uint2 afl[4][6];
                #pragma unroll
                for (int pk = 0; pk < 4; pk++)
                    #pragma unroll
                    for (int e = 0; e < 6; e++) {
                        int row = r0 + (e >> 1) * 16 + (e & 1) * 8;
                        afl[pk][e] = __ldcg((const uint2*)(hin + (size_t)row * 256
                                                           + pk * 8 + q * 2));
                    }
                #pragma unroll 4
                for (int kg = 0; kg < 32; kg++) {
                    const int sl = kg & 3;
                    uint32_t af[3][4];
                    #pragma unroll
                    for (int mf = 0; mf < 3; mf++) {
                        af[mf][0] = afl[sl][2 * mf].x;
                        af[mf][1] = afl[sl][2 * mf + 1].x;
                        af[mf][2] = afl[sl][2 * mf].y;
                        af[mf][3] = afl[sl][2 * mf + 1].y;
                    }
                    if (kg + 4 < 32) {
                        #pragma unroll
                        for (int e = 0; e < 6; e++) {
                            int row = r0 + (e >> 1) * 16 + (e & 1) * 8;
                            afl[sl][e] = __ldcg((const uint2*)(hin + (size_t)row * 256
                                                               + (kg + 4) * 8 + q * 2));
                        }
                    }
                    #pragma unroll
                    for (int nf = 0; nf < 4; nf++) {
                        int nl = wn + nf * 8 + p;
                        uint2 pb = *(const uint2*)&Bh[kg * 512 + nl * 8 + q * 2];
                        uint32_t bf[2] = {pb.x, pb.y};
                        #pragma unroll
                        for (int mf = 0; mf < 3; mf++)
                            mma16(acc[mf][nf], af[mf], bf);
                    }
                }
            }

            // cell epilogue (shfl-free, smem c-state)
            #pragma unroll
            for (int mf = 0; mf < 3; mf++) {
                int rl0 = wm + mf * 16 + p;
                #pragma unroll
                for (int nfp = 0; nfp < 2; nfp++) {
                    int j0 = mf * 4 + 2 * nfp;
                    int j1 = j0 + 1;
                    float2 ia = __half22float2(*(__half2*)&gxw[j0 * 2]);
                    float2 ib = __half22float2(*(__half2*)&gxw[j0 * 2 + 1]);
                    float2 fa = __half22float2(*(__half2*)&gxw[j1 * 2]);
                    float2 fb = __half22float2(*(__half2*)&gxw[j1 * 2 + 1]);
                    int ul = (wn >> 5) * 8 + nfp * 4 + q;
                    int gu = (n0 >> 2) + ul;
                    int jj   = (gu >> 1) & 7;
                    int hidx = (gu >> 4) * 16 + ((jj & 3) * 2 + (jj >> 2)) * 2 + (gu & 1);

                    #pragma unroll
                    for (int rh = 0; rh < 2; rh++) {
                        int rl = rl0 + rh * 8;
                        float zi = acc[mf][2 * nfp][2 * rh]     + (rh ? ib.x : ia.x);
                        float zj = acc[mf][2 * nfp][2 * rh + 1] + (rh ? ib.y : ia.y);
                        float zf = acc[mf][2 * nfp + 1][2 * rh]     + (rh ? fb.x : fa.x);
                        float zo = acc[mf][2 * nfp + 1][2 * rh + 1] + (rh ? fb.y : fa.y);

                        float ig = fsig(zi);
                        float fg = fsig(zf);
                        float og = fsig(zo);
                        float cp = csm[rl * 16 + ul];
                        float cn = fg * cp + ig * ftanh(zj);
                        float hn = og * ftanh(cn);
                        csm[rl * 16 + ul] = cn;

                        int grow = m0 + rl;
                        ((__half*)hout)[(size_t)grow * HID + hidx] = __float2half_rn(hn);
                        if (LAST && t == SEQ - 1)
                            h_final[(size_t)grow * HID + gu] = hn;
                    }
                }
            }

            // barrier ARRIVE (after all warps' h stores)
            __syncthreads();
            if (tid == 0) {
                __threadfence();
                unsigned int old = atomicAdd(&g_bar_count, 1);
                if (old == NCTA - 1) {
                    g_bar_count = 0;
                    __threadfence();
                    atomicAdd(&g_bar_phase, 1);
                }
            }
        }

        // ---------------- phase 2: x-GEMM inside barrier window -------------
        if (FUSE_X && t > 0) {
            float accx[3][4][4] = {};
            uint2 afl[4][6];
            #pragma unroll
            for (int pk = 0; pk < 4; pk++)
                #pragma unroll
                for (int e = 0; e < 6; e++) {
                    int row = r0 + (e >> 1) * 16 + (e & 1) * 8;
                    afl[pk][e] = __ldcg((const uint2*)(hin + (size_t)row * 256
                                                       + pk * 8 + q * 2));
                }
            #pragma unroll 4
            for (int kg = 0; kg < 32; kg++) {
                const int sl = kg & 3;
                uint32_t af[3][4];
                #pragma unroll
                for (int mf = 0; mf < 3; mf++) {
                    af[mf][0] = afl[sl][2 * mf].x;
                    af[mf][1] = afl[sl][2 * mf + 1].x;
                    af[mf][2] = afl[sl][2 * mf].y;
                    af[mf][3] = afl[sl][2 * mf + 1].y;
                }
                if (kg + 4 < 32) {
                    #pragma unroll
                    for (int e = 0; e < 6; e++) {
                        int row = r0 + (e >> 1) * 16 + (e & 1) * 8;
                        afl[sl][e] = __ldcg((const uint2*)(hin + (size_t)row * 256
                                                           + (kg + 4) * 8 + q * 2));
                    }
                }
                #pragma unroll
                for (int nf = 0; nf < 4; nf++) {
                    int nl = wn + nf * 8 + p;
                    uint2 pb = *(const uint2*)&Bx[kg * 512 + nl * 8 + q * 2];
                    uint32_t bf[2] = {pb.x, pb.y};
                    #pragma unroll
                    for (int mf = 0; mf < 3; mf++)
                        mma16(accx[mf][nf], af[mf], bf);
                }
            }

            // x-epilogue: 6 STG.128 of contiguous fp16 gx words.
            uint32_t gxo[24];
            #pragma unroll
            for (int mf = 0; mf < 3; mf++) {
                #pragma unroll
                for (int nf = 0; nf < 4; nf++) {
                    int ncl = wn + nf * 8 + 2 * q;
                    float b0 = biasx[ncl], b1 = biasx[ncl + 1];
                    __half2 h0 = __floats2half2_rn(accx[mf][nf][0] + b0,
                                                   accx[mf][nf][1] + b1);
                    __half2 h1 = __floats2half2_rn(accx[mf][nf][2] + b0,
                                                   accx[mf][nf][3] + b1);
                    gxo[(mf * 4 + nf) * 2]     = *(uint32_t*)&h0;
                    gxo[(mf * 4 + nf) * 2 + 1] = *(uint32_t*)&h1;
                }
            }
            size_t base = ((((size_t)(t - 1) * 128 + blockIdx.x) * 8 + warp) * 32
                           + lane) * 24;
            #pragma unroll
            for (int j = 0; j < 6; j++)
                *(uint4*)(gx_out + base + j * 4) = *(uint4*)(gxo + j * 4);
        }

        // Prefetch next step's gx.
        if (t + 1 < SEQ) {
            const uint4* gp = (const uint4*)gx +
                ((((size_t)(t + 1) * 128 + blockIdx.x) * 8 + warp) * 32 + lane) * 6;
            #pragma unroll
            for (int j = 0; j < 6; j++) *(uint4*)(gxw + j * 4) = gp[j];
        }

        // ---------------- phase 3: per-warp barrier WAIT ---------------------
        if (t < SEQ) {
            if (lane == 0) {
                while (ld_acq(&g_bar_phase) == phase) { }
            }
            __syncwarp();
            phase++;
        }
    }
}

// ---------------------------------------------------------------------------
// SELU + head kernels (unchanged, fp32)
// ---------------------------------------------------------------------------
__device__ __forceinline__ float selu_f(float x) {
    const float sc = 1.0507009873554805f;
    const float al = 1.6732632423543772f;
    return x > 0.f ? sc * x : sc * al * expm1f(x);
}

template <bool BIAS, bool SELU>
__global__ void __launch_bounds__(256, 2)
sgemm128(const float* __restrict__ A, const float* __restrict__ B,
         float* __restrict__ C, int M, int N, int K,
         const float* __restrict__ bias) {
    __shared__ float As[16][128];
    __shared__ float Bs[16][128];

    const int bm  = blockIdx.y * 128;
    const int bn  = blockIdx.x * 128;
    const int tid = threadIdx.x;
    const int tx  = (tid & 15) * 8;
    const int ty  = (tid >> 4) * 8;

    float acc[8][8] = {};

    const int arow = tid >> 2;
    const int acol = (tid & 3) << 2;
    const int brow = tid >> 5;
    const int bcol = (tid & 31) << 2;

    const float* Aptr = A + (size_t)(bm + arow) * K + acol;
    const float* Bptr = B + (size_t)brow * N + bn + bcol;

    for (int k0 = 0; k0 < K; k0 += 16) {
        float4 a0 = *(const float4*)(Aptr);
        float4 a1 = *(const float4*)(Aptr + (size_t)64 * K);
        float4 b0 = *(const float4*)(Bptr);
        float4 b1 = *(const float4*)(Bptr + (size_t)8 * N);

        As[acol + 0][arow]      = a0.x;
        As[acol + 1][arow]      = a0.y;
        As[acol + 2][arow]      = a0.z;
        As[acol + 3][arow]      = a0.w;
        As[acol + 0][arow + 64] = a1.x;
        As[acol + 1][arow + 64] = a1.y;
        As[acol + 2][arow + 64] = a1.z;
        As[acol + 3][arow + 64] = a1.w;
        *(float4*)&Bs[brow][bcol]     = b0;
        *(float4*)&Bs[brow + 8][bcol] = b1;
        __syncthreads();

        #pragma unroll
        for (int kk = 0; kk < 16; kk++) {
            float ar[8], br[8];
            *(float4*)(ar)     = *(const float4*)&As[kk][ty];
            *(float4*)(ar + 4) = *(const float4*)&As[kk][ty + 4];
            *(float4*)(br)     = *(const float4*)&Bs[kk][tx];
            *(float4*)(br + 4) = *(const float4*)&Bs[kk][tx + 4];
            #pragma unroll
            for (int i = 0; i < 8; i++)
                #pragma unroll
                for (int j = 0; j < 8; j++)
                    acc[i][j] += ar[i] * br[j];
        }
        __syncthreads();

        Aptr += 16;
        Bptr += (size_t)16 * N;
    }

    float bv[8];
    if (BIAS) {
        #pragma unroll
        for (int j = 0; j < 8; j++) bv[j] = bias[bn + tx + j];
    }

    #pragma unroll
    for (int i = 0; i < 8; i++) {
        float v[8];
        #pragma unroll
        for (int j = 0; j < 8; j++) {
            float x = acc[i][j];
            if (BIAS) x += bv[j];
            if (SELU) x = selu_f(x);
            v[j] = x;
        }
        float* crow = C + (size_t)(bm + ty + i) * N + bn + tx;
        *(float4*)(crow)     = *(float4*)(v);
        *(float4*)(crow + 4) = *(float4*)(v + 4);
    }
}

__global__ void bn1_kernel(const float* __restrict__ h, const float* __restrict__ gamma,
                           const float* __restrict__ beta, float* __restrict__ y) {
    int f = blockIdx.x;
    int r = threadIdx.x;
    int s = f >> 9;
    int j = f & 511;
    float v = h[((size_t)(s * BATCH + r)) * HID + j];

    __shared__ float sd[256];
    sd[r] = v; __syncthreads();
    for (int w = 128; w > 0; w >>= 1) { if (r < w) sd[r] += sd[r + w]; __syncthreads(); }
    float mu = sd[0] * (1.f / 256.f);
    __syncthreads();
    float d = v - mu;
    sd[r] = d * d; __syncthreads();
    for (int w = 128; w > 0; w >>= 1) { if (r < w) sd[r] += sd[r + w]; __syncthreads(); }
    float var = sd[0] * (1.f / 256.f);

    float sc = gamma[f] * rsqrtf(var + 1e-3f);
    y[r * 1536 + f] = d * sc + beta[f];
}

__global__ void bn_kernel(const float* __restrict__ x, const float* __restrict__ gamma,
                          const float* __restrict__ beta, float* __restrict__ y,
                          int stride) {
    int f = blockIdx.x;
    int r = threadIdx.x;
    float v = x[(size_t)r * stride + f];

    __shared__ float sd[256];
    sd[r] = v; __syncthreads();
    for (int w = 128; w > 0; w >>= 1) { if (r < w) sd[r] += sd[r + w]; __syncthreads(); }
    float mu = sd[0] * (1.f / 256.f);
    __syncthreads();
    float d = v - mu;
    sd[r] = d * d; __syncthreads();
    for (int w = 128; w > 0; w >>= 1) { if (r < w) sd[r] += sd[r + w]; __syncthreads(); }
    float var = sd[0] * (1.f / 256.f);

    float sc = gamma[f] * rsqrtf(var + 1e-3f);
    y[(size_t)r * stride + f] = d * sc + beta[f];
}

__global__ void pad_w2(const float* __restrict__ W2, const float* __restrict__ b2,
                       float* __restrict__ w2p, float* __restrict__ b2p) {
    int idx = blockIdx.x * 256 + threadIdx.x;
    int n = idx & 127;
    int k = idx >> 7;
    w2p[idx] = (n < 102) ? W2[k * 102 + n] : 0.f;
    if (idx < 128) b2p[idx] = (idx < 102) ? b2[idx] : 0.f;
}

__global__ void out_kernel(const float* __restrict__ a, const float* __restrict__ W3,
                           const float* __restrict__ b3, float* __restrict__ out) {
    int idx = blockIdx.x * 256 + threadIdx.x;
    int b = idx >> 2;
    int n = idx & 3;
    float acc = b3[n];
    #pragma unroll 6
    for (int k = 0; k < 102; k++)
        acc += a[b * 128 + k] * W3[k * 4 + n];
    out[idx] = acc;
}

// ---------------------------------------------------------------------------
// Launch
// ---------------------------------------------------------------------------
extern "C" void kernel_launch(void* const* d_in, const int* in_sizes, int n_in,
                              void* d_out, int out_size) {
    const int*   t1   = (const int*)d_in[0];
    const int*   t2   = (const int*)d_in[1];
    const int*   t3   = (const int*)d_in[2];
    const float* emb  = (const float*)d_in[3];
    const float* lw   = (const float*)d_in[4];
    const float* lb   = (const float*)d_in[5];
    const float* bn1g = (const float*)d_in[6];
    const float* bn1b = (const float*)d_in[7];
    const float* W1   = (const float*)d_in[8];
    const float* b1   = (const float*)d_in[9];
    const float* bn2g = (const float*)d_in[10];
    const float* bn2b = (const float*)d_in[11];
    const float* W2   = (const float*)d_in[12];
    const float* b2   = (const float*)d_in[13];
    const float* bn3g = (const float*)d_in[14];
    const float* bn3b = (const float*)d_in[15];
    const float* W3   = (const float*)d_in[16];
    const float* b3   = (const float*)d_in[17];
    float* out = (float*)d_out;

    uint32_t *seqH, *gxA, *gxB, *hPa, *hPb, *wxp, *whp;
    float *hf, *bp;
    float *xn1, *a1, *xn2, *w2p, *b2p, *a2, *a2n;
    cudaGetSymbolAddress((void**)&seqH, g_seqH);
    cudaGetSymbolAddress((void**)&gxA,  g_gxA);
    cudaGetSymbolAddress((void**)&gxB,  g_gxB);
    cudaGetSymbolAddress((void**)&hPa,  g_hPa);
    cudaGetSymbolAddress((void**)&hPb,  g_hPb);
    cudaGetSymbolAddress((void**)&hf,   g_hf);
    cudaGetSymbolAddress((void**)&wxp,  g_WxP);
    cudaGetSymbolAddress((void**)&whp,  g_WhP);
    cudaGetSymbolAddress((void**)&bp,   g_bp);
    cudaGetSymbolAddress((void**)&xn1,  g_xn1);
    cudaGetSymbolAddress((void**)&a1,   g_a1);
    cudaGetSymbolAddress((void**)&xn2,  g_xn2);
    cudaGetSymbolAddress((void**)&w2p,  g_W2p);
    cudaGetSymbolAddress((void**)&b2p,  g_b2p);
    cudaGetSymbolAddress((void**)&a2,   g_a2);
    cudaGetSymbolAddress((void**)&a2n,  g_a2n);

    cudaFuncSetAttribute(lstm_layer<true, false>,
                         cudaFuncAttributeMaxDynamicSharedMemorySize, SMF_BYTES);
    cudaFuncSetAttribute(lstm_layer<false, true>,
                         cudaFuncAttributeMaxDynamicSharedMemorySize, SMP_BYTES);
    cudaFuncSetAttribute(gemm_x_f16,
                         cudaFuncAttributeMaxDynamicSharedMemorySize, X_BYTES);

    prep_kernel<<<(3 * 1024 * G4) / 256, 256>>>(lw, lb, wxp, whp, bp);
    embed_kernel<<<BB * SEQ, 128>>>(t1, t2, t3, emb, (__half2*)seqH);

    const size_t LSL = (size_t)32 * 16384;

    // Layer 0: x-GEMM from embeddings; fused recurrence emits layer-1 gx.
    gemm_x_f16<<<dim3(32, (BB * SEQ) / 128), 256, X_BYTES>>>(seqH, wxp, bp, gxA);
    lstm_layer<true, false><<<NCTA, 256, SMF_BYTES>>>(
        whp, wxp + LSL, gxA, bp + G4, hPa, hPb, gxB, hf);

    // Layer 1: fused recurrence emits layer-2 gx.
    lstm_layer<true, false><<<NCTA, 256, SMF_BYTES>>>(
        whp + LSL, wxp + 2 * LSL, gxB, bp + 2 * G4, hPa, hPb, gxA, hf);

    // Layer 2: plain recurrence, writes final hidden state.
    lstm_layer<false, true><<<NCTA, 256, SMP_BYTES>>>(
        whp + 2 * LSL, nullptr, gxA, nullptr, hPa, hPb, gxB, hf);

    bn1_kernel<<<1536, 256>>>(hf, bn1g, bn1b, xn1);
    sgemm128<true, true><<<dim3(1024 / 128, BATCH / 128), 256>>>(
        xn1, W1, a1, BATCH, 1024, 1536, b1);
    bn_kernel<<<1024, 256>>>(a1, bn2g, bn2b, xn2, 1024);
    pad_w2<<<(1024 * 128) / 256, 256>>>(W2, b2, w2p, b2p);
    sgemm128<true, true><<<dim3(1, BATCH / 128), 256>>>(
        xn2, w2p, a2, BATCH, 128, 1024, b2p);
    bn_kernel<<<102, 256>>>(a2, bn3g, bn3b, a2n, 128);
    out_kernel<<<4, 256>>>(a2n, W3, b3, out);
}

// round 17
// speedup vs baseline: 1.1318x; 1.1318x over previous
#include <cuda_runtime.h>
#include <cuda_fp16.h>
#include <math.h>
#include <stdint.h>

// ---------------------------------------------------------------------------
// Problem constants
// ---------------------------------------------------------------------------
static constexpr int BATCH = 256;
static constexpr int SEQ   = 128;
static constexpr int HID   = 512;
static constexpr int G4    = 2048;
static constexpr int BB    = 768;

static constexpr int NCTA   = 128;
static constexpr int M_TILE = 192;
// Fused layer smem: merged Wh|Wx slice (32 kg x 64 col x 16 words) + c + bias
static constexpr int SMF_BW    = 32 * 64 * 16;              // 32768 words
static constexpr int SMF_WORDS = SMF_BW + M_TILE * 16 + 64; // 35904
static constexpr int SMF_BYTES = SMF_WORDS * 4;             // 143616
// Plain layer smem: Wh slice (32 kg x 512 words) + c
static constexpr int SMP_BW    = 32 * 512;                  // 16384 words
static constexpr int SMP_WORDS = SMP_BW + M_TILE * 16;      // 19456
static constexpr int SMP_BYTES = SMP_WORDS * 4;             // 77824

// gemm_x (layer 0)
static constexpr int XA_KGW = 128 * 8 + 8;
static constexpr int X_B = 0;
static constexpr int X_A = 16384;
static constexpr int X_WORDS = X_A + 2 * 4 * XA_KGW;
static constexpr int X_BYTES = X_WORDS * 4;

// ---------------------------------------------------------------------------
// Scratch (device globals; no runtime allocation allowed)
// ---------------------------------------------------------------------------
__device__ uint32_t g_seqH[(size_t)BB * SEQ * 256];     // permuted fp16 embeddings
__device__ uint32_t g_gxA [(size_t)BB * SEQ * G4 / 2];  // fp16 gx ping (frag layout)
__device__ uint32_t g_gxB [(size_t)BB * SEQ * G4 / 2];  // fp16 gx pong
__device__ uint32_t g_hPa [(size_t)BB * 256];           // permuted fp16 h ping
__device__ uint32_t g_hPb [(size_t)BB * 256];           // permuted fp16 h pong
__device__ float    g_hf  [(size_t)BB * HID];           // exact fp32 final h
__device__ uint32_t g_Wx0P[(size_t)32 * 16384];         // layer-0 Wx slices (packed)
__device__ uint32_t g_mrg [(size_t)2 * 32 * 32768];     // merged Wh(l)|Wx(l+1)
__device__ uint32_t g_Wh2P[(size_t)32 * 16384];         // layer-2 Wh slices (packed)
__device__ float    g_bp  [3 * G4];
__device__ float    g_xn1 [BATCH * 1536];
__device__ float    g_a1  [BATCH * 1024];
__device__ float    g_xn2 [BATCH * 1024];
__device__ float    g_W2p [1024 * 128];
__device__ float    g_b2p [128];
__device__ float    g_a2  [BATCH * 128];
__device__ float    g_a2n [BATCH * 128];

// Grid barrier state (monotonic phase; graph-replay safe)
__device__ unsigned int g_bar_count;
__device__ unsigned int g_bar_phase;

// ---------------------------------------------------------------------------
// Helpers
// ---------------------------------------------------------------------------
__device__ __forceinline__ void mma16(float* c, const uint32_t* a, const uint32_t* b) {
    asm volatile(
        "mma.sync.aligned.m16n8k16.row.col.f32.f16.f16.f32 "
        "{%0,%1,%2,%3}, {%4,%5,%6,%7}, {%8,%9}, {%0,%1,%2,%3};"
        : "+f"(c[0]), "+f"(c[1]), "+f"(c[2]), "+f"(c[3])
        : "r"(a[0]), "r"(a[1]), "r"(a[2]), "r"(a[3]), "r"(b[0]), "r"(b[1]));
}

__device__ __forceinline__ unsigned int ld_acq(const unsigned int* p) {
    unsigned int v;
    asm volatile("ld.acquire.gpu.u32 %0, [%1];" : "=r"(v) : "l"(p));
    return v;
}

__device__ __forceinline__ float fsig(float x) {
    return __fdividef(1.f, 1.f + __expf(-x));
}
__device__ __forceinline__ float ftanh(float x) {
    return __fdividef(2.f, 1.f + __expf(-2.f * x)) - 1.f;
}

__device__ __forceinline__ int kperm_word(int u) {        // u even; word index
    int j = (u >> 1) & 7;
    return (u >> 4) * 8 + (j & 3) * 2 + (j >> 2);
}

// N-side gate-to-column mapping (shfl-free epilogue).
__device__ __forceinline__ int gate_col(int u_loc, int g) {
    int wni = u_loc >> 3, u7 = u_loc & 7;
    int nfp = u7 >> 2, qq = u7 & 3;
    return wni * 32 + (nfp * 2 + (g >> 1)) * 8 + qq * 2 + (g & 1);
}

// ---------------------------------------------------------------------------
// gx fragment-native mapping, fp16 (consumer: 8 warps, warp tile 48x32).
// ---------------------------------------------------------------------------
__device__ __forceinline__ void store_gx_frag_h(uint32_t* gxL, int r, int n, float2 v) {
    int t   = r & 127, bb = r >> 7;
    int mb  = bb / 192, rl = bb - mb * 192;
    int wmi = rl / 48,  rlp = rl - wmi * 48;
    int mfl = rlp >> 4, pp = rlp & 15;
    int nb  = n >> 6,   ncl = n & 63;
    int wni = ncl >> 5, ncl2 = ncl & 31;
    int nfl = ncl2 >> 3, ql = (ncl2 & 7) >> 1;
    size_t idx = ((((size_t)t * 128 + mb * 32 + nb) * 8 + wmi * 2 + wni) * 32
                  + (pp & 7) * 4 + ql) * 24 + (mfl * 4 + nfl) * 2 + (pp >> 3);
    __half2 h = __floats2half2_rn(v.x, v.y);
    gxL[idx] = *(uint32_t*)&h;
}

// ---------------------------------------------------------------------------
// Embedding gather -> permuted fp16
// ---------------------------------------------------------------------------
__global__ void embed_kernel(const int* __restrict__ t1, const int* __restrict__ t2,
                             const int* __restrict__ t3, const float* __restrict__ emb,
                             __half2* __restrict__ out) {
    int bbt = blockIdx.x;
    int bb  = bbt >> 7;
    int t   = bbt & 127;
    int s   = bb >> 8;
    int b   = bb & 255;
    const int* txt = (s == 0) ? t1 : (s == 1 ? t2 : t3);
    int tok = txt[b * SEQ + t];
    int u0  = threadIdx.x * 4;
    float4 v = *(const float4*)(emb + (size_t)tok * HID + u0);
    __half2* dst = out + (size_t)bbt * 256;
    dst[kperm_word(u0)]     = __floats2half2_rn(v.x, v.y);
    dst[kperm_word(u0 + 2)] = __floats2half2_rn(v.z, v.w);
}

// ---------------------------------------------------------------------------
// Weight/bias permutation.
//  Wx layer 0 -> g_Wx0P  [slice][kg][col*8 + wpos]
//  Wh l (l=0,1) + Wx l+1 -> g_mrg[pair l] [slice][kg][col*16 + q*4 + {wh|wx}]
//  Wh layer 2 -> g_Wh2P  [slice][kg][col*8 + wpos]
// ---------------------------------------------------------------------------
__global__ void prep_kernel(const float* __restrict__ lw, const float* __restrict__ lb,
                            uint32_t* __restrict__ wx0p, uint32_t* __restrict__ mrg,
                            uint32_t* __restrict__ wh2p, float* __restrict__ bp) {
    int idx = blockIdx.x * 256 + threadIdx.x;
    int l   = idx / (1024 * G4);
    int rem = idx - l * 1024 * G4;
    int k   = rem / G4;
    int n   = rem - k * G4;
    int u   = n >> 2, g = n & 3;
    float v = lw[(size_t)l * 1024 * G4 + (size_t)k * G4 + g * HID + u];
    __half hv = __float2half_rn(v);

    int s = u >> 4;
    int c = gate_col(u & 15, g);
    int kk = (k < HID) ? k : (k - HID);
    int kg = kk >> 4, j = (kk >> 1) & 7;
    int wpos = (j & 3) * 2 + (j >> 2);
    int half = kk & 1;
    int mw_wh = (wpos >> 1) * 4 + (wpos & 1);     // merged word pos for Wh
    if (k < HID) {
        if (l == 0) {
            size_t hidx = ((((size_t)s * 32 + kg) * 512) + c * 8 + wpos) * 2 + half;
            ((__half*)wx0p)[hidx] = hv;
        } else {
            size_t hidx = (((((size_t)(l - 1) * 32 + s) * 32 + kg) * 1024)
                           + c * 16 + mw_wh + 2) * 2 + half;
            ((__half*)mrg)[hidx] = hv;
        }
    } else {
        if (l < 2) {
            size_t hidx = (((((size_t)l * 32 + s) * 32 + kg) * 1024)
                           + c * 16 + mw_wh) * 2 + half;
            ((__half*)mrg)[hidx] = hv;
        } else {
            size_t hidx = ((((size_t)s * 32 + kg) * 512) + c * 8 + wpos) * 2 + half;
            ((__half*)wh2p)[hidx] = hv;
        }
    }
    if (idx < 3 * G4) {
        int ll = idx / G4, nn = idx - ll * G4;
        int uu = nn >> 2, gg = nn & 3;
        int ss = uu >> 4, cc = gate_col(uu & 15, gg);
        bp[ll * G4 + ss * 64 + cc] = lb[ll * G4 + gg * HID + uu];
    }
}

// ---------------------------------------------------------------------------
// Layer-0 x-GEMM (fp16 mma): gx = emb @ Wx0 + b0, fp16 fragment-native out.
// ---------------------------------------------------------------------------
__global__ void __launch_bounds__(256)
gemm_x_f16(const uint32_t* __restrict__ A, const uint32_t* __restrict__ BP,
           const float* __restrict__ bias, uint32_t* __restrict__ gxL) {
    extern __shared__ uint32_t xs[];
    uint32_t* Bs = xs + X_B;
    uint32_t* As = xs + X_A;

    const int tid  = threadIdx.x;
    const int lane = tid & 31, warp = tid >> 5;
    const int q    = lane & 3;
    const int p    = lane >> 2;
    const int wm   = (warp >> 1) * 32;
    const int wn   = (warp & 1) * 32;
    const int m0   = blockIdx.y * 128;
    const int n0   = blockIdx.x * 64;

    {
        const uint4* src = (const uint4*)(BP + (size_t)blockIdx.x * 16384);
        #pragma unroll
        for (int i = 0; i < 16; i++)
            *(uint4*)(Bs + (tid + i * 256) * 4) = src[tid + i * 256];
    }

    float acc[2][4][4] = {};

    uint4 v[4];
    {
        #pragma unroll
        for (int i = 0; i < 4; i++) {
            int idx = tid + i * 256;
            int row = idx >> 3, part = idx & 7;
            v[i] = *((const uint4*)A + (size_t)(m0 + row) * 64 + part);
        }
    }
    __syncthreads();

    #pragma unroll 1
    for (int ct = 0; ct <= 8; ct++) {
        __syncthreads();
        if (ct < 8) {
            uint32_t* Ab = As + (ct & 1) * (4 * XA_KGW);
            #pragma unroll
            for (int i = 0; i < 4; i++) {
                int idx = tid + i * 256;
                int row = idx >> 3, part = idx & 7;
                *(uint4*)(Ab + (part >> 1) * XA_KGW + row * 8 + (part & 1) * 4) = v[i];
            }
        }
        if (ct < 7) {
            #pragma unroll
            for (int i = 0; i < 4; i++) {
                int idx = tid + i * 256;
                int row = idx >> 3, part = idx & 7;
                v[i] = *((const uint4*)A + (size_t)(m0 + row) * 64 + (ct + 1) * 8 + part);
            }
        }
        if (ct >= 1) {
            const uint32_t* Ab2 = As + ((ct - 1) & 1) * (4 * XA_KGW);
            #pragma unroll
            for (int kgl = 0; kgl < 4; kgl++) {
                const int kg = (ct - 1) * 4 + kgl;
                uint32_t af[2][4];
                #pragma unroll
                for (int mf = 0; mf < 2; mf++) {
                    int rl = wm + mf * 16 + p;
                    uint2 p0 = *(const uint2*)&Ab2[kgl * XA_KGW + rl * 8 + q * 2];
                    uint2 p1 = *(const uint2*)&Ab2[kgl * XA_KGW + (rl + 8) * 8 + q * 2];
                    af[mf][0] = p0.x; af[mf][1] = p1.x;
                    af[mf][2] = p0.y; af[mf][3] = p1.y;
                }
                #pragma unroll
                for (int nf = 0; nf < 4; nf++) {
                    int nl = wn + nf * 8 + p;
                    uint2 pb = *(const uint2*)&Bs[kg * 512 + nl * 8 + q * 2];
                    uint32_t bf[2] = {pb.x, pb.y};
                    #pragma unroll
                    for (int mf = 0; mf < 2; mf++)
                        mma16(acc[mf][nf], af[mf], bf);
                }
            }
        }
    }

    #pragma unroll
    for (int mf = 0; mf < 2; mf++) {
        int r = m0 + wm + mf * 16 + p;
        #pragma unroll
        for (int nf = 0; nf < 4; nf++) {
            int n = n0 + wn + nf * 8 + 2 * q;
            float b0 = bias[n], b1 = bias[n + 1];
            float2 v0 = make_float2(acc[mf][nf][0] + b0, acc[mf][nf][1] + b1);
            float2 v1 = make_float2(acc[mf][nf][2] + b0, acc[mf][nf][3] + b1);
            store_gx_frag_h(gxL, r,     n, v0);
            store_gx_frag_h(gxL, r + 8, n, v1);
        }
    }
}

// ---------------------------------------------------------------------------
// Persistent LSTM layer (R14 winner + per-warp barrier wait):
// direct-LDG A fragments, merged Wh|Wx smem B (fused) or plain Wh B,
// shfl-free epilogue, fast transcendentals, arrive-early grid barrier,
// batched x-epilogue STG.128. R17: tail wait is per-warp (lane0 spin +
// __syncwarp) instead of CTA-wide — safe because writes to hbuf[t&1] only
// happen after observing the phase flip, which itself requires every CTA's
// post-read __syncthreads + arrive.
// ---------------------------------------------------------------------------
template <bool FUSE_X, bool LAST>
__global__ void __launch_bounds__(256, 1)
lstm_layer(const uint32_t* __restrict__ BW, const uint32_t* __restrict__ gx,
           const float* __restrict__ bias_n,
           uint32_t* __restrict__ hA, uint32_t* __restrict__ hB,
           uint32_t* __restrict__ gx_out, float* __restrict__ h_final) {
    extern __shared__ uint32_t smem[];
    constexpr int BW_WORDS = FUSE_X ? SMF_BW : SMP_BW;
    uint32_t* BWs   = smem;
    float*    csm   = (float*)(smem + BW_WORDS);
    float*    biasx = csm + M_TILE * 16;

    const int tid  = threadIdx.x;
    const int lane = tid & 31, warp = tid >> 5;
    const int q    = lane & 3;
    const int p    = lane >> 2;
    const int wm   = (warp >> 1) * 48;
    const int wn   = (warp & 1) * 32;
    const int m0   = (blockIdx.x >> 5) * M_TILE;
    const int n0   = (blockIdx.x & 31) * 64;

    unsigned int phase = 0;
    if (lane == 0) phase = ld_acq(&g_bar_phase);

    // Resident B slice copy
    {
        const uint4* src = (const uint4*)(BW + (size_t)(blockIdx.x & 31) * BW_WORDS);
        #pragma unroll
        for (int i = 0; i < BW_WORDS / 1024; i++)
            *(uint4*)(BWs + (tid + i * 256) * 4) = src[tid + i * 256];
    }
    if (FUSE_X && tid < 64) biasx[tid] = bias_n[n0 + tid];
    for (int i = tid; i < M_TILE * 16; i += 256) csm[i] = 0.f;
    __syncthreads();

    // Prefetch gx fragments for t = 0.
    uint32_t gxw[24];
    {
        const uint4* gp = (const uint4*)gx +
            ((((size_t)0 * 128 + blockIdx.x) * 8 + warp) * 32 + lane) * 6;
        #pragma unroll
        for (int j = 0; j < 6; j++) *(uint4*)(gxw + j * 4) = gp[j];
    }

    const int r0 = m0 + wm + p;

    const int tEnd = FUSE_X ? SEQ : SEQ - 1;
    for (int t = 0; t <= tEnd; t++) {
        const uint32_t* hin  = (t & 1) ? hB : hA;
        uint32_t*       hout = (t & 1) ? hA : hB;

        float acc [3][4][4] = {};
        float accx[3][4][4] = {};

        if (t > 0) {
            uint2 afl[4][6];
            #pragma unroll
            for (int pk = 0; pk < 4; pk++)
                #pragma unroll
                for (int e = 0; e < 6; e++) {
                    int row = r0 + (e >> 1) * 16 + (e & 1) * 8;
                    afl[pk][e] = __ldcg((const uint2*)(hin + (size_t)row * 256
                                                       + pk * 8 + q * 2));
                }
            #pragma unroll 4
            for (int kg = 0; kg < 32; kg++) {
                const int sl = kg & 3;
                uint32_t af[3][4];
                #pragma unroll
                for (int mf = 0; mf < 3; mf++) {
                    af[mf][0] = afl[sl][2 * mf].x;  af[mf][1] = afl[sl][2 * mf + 1].x;
                    af[mf][2] = afl[sl][2 * mf].y;  af[mf][3] = afl[sl][2 * mf + 1].y;
                }
                if (kg + 4 < 32) {
                    #pragma unroll
                    for (int e = 0; e < 6; e++) {
                        int row = r0 + (e >> 1) * 16 + (e & 1) * 8;
                        afl[sl][e] = __ldcg((const uint2*)(hin + (size_t)row * 256
                                                           + (kg + 4) * 8 + q * 2));
                    }
                }
                if (FUSE_X) {
                    #pragma unroll
                    for (int nf = 0; nf < 4; nf++) {
                        int nl = wn + nf * 8 + p;
                        uint4 m = *(const uint4*)&BWs[kg * 1024 + nl * 16 + q * 4];
                        uint32_t bh[2] = {m.x, m.y};
                        uint32_t bx[2] = {m.z, m.w};
                        if (t < SEQ) {
                            #pragma unroll
                            for (int mf = 0; mf < 3; mf++)
                                mma16(acc[mf][nf], af[mf], bh);
                        }
                        #pragma unroll
                        for (int mf = 0; mf < 3; mf++)
                            mma16(accx[mf][nf], af[mf], bx);
                    }
                } else {
                    #pragma unroll
                    for (int nf = 0; nf < 4; nf++) {
                        int nl = wn + nf * 8 + p;
                        uint2 pb = *(const uint2*)&BWs[kg * 512 + nl * 8 + q * 2];
                        uint32_t bh[2] = {pb.x, pb.y};
                        #pragma unroll
                        for (int mf = 0; mf < 3; mf++)
                            mma16(acc[mf][nf], af[mf], bh);
                    }
                }
            }
        }

        // h-epilogue (shfl-free): gates (i,j) in frag 2*nfp, (f,o) in 2*nfp+1.
        if (t < SEQ) {
            #pragma unroll
            for (int mf = 0; mf < 3; mf++) {
                int rl0 = wm + mf * 16 + p;
                #pragma unroll
                for (int nfp = 0; nfp < 2; nfp++) {
                    int j0 = mf * 4 + 2 * nfp;
                    int j1 = j0 + 1;
                    float2 ia = __half22float2(*(__half2*)&gxw[j0 * 2]);
                    float2 ib = __half22float2(*(__half2*)&gxw[j0 * 2 + 1]);
                    float2 fa = __half22float2(*(__half2*)&gxw[j1 * 2]);
                    float2 fb = __half22float2(*(__half2*)&gxw[j1 * 2 + 1]);
                    int ul = (wn >> 5) * 8 + nfp * 4 + q;
                    int gu = (n0 >> 2) + ul;
                    int jj   = (gu >> 1) & 7;
                    int hidx = (gu >> 4) * 16 + ((jj & 3) * 2 + (jj >> 2)) * 2 + (gu & 1);

                    #pragma unroll
                    for (int rh = 0; rh < 2; rh++) {
                        int rl = rl0 + rh * 8;
                        float zi = acc[mf][2 * nfp][2 * rh]     + (rh ? ib.x : ia.x);
                        float zj = acc[mf][2 * nfp][2 * rh + 1] + (rh ? ib.y : ia.y);
                        float zf = acc[mf][2 * nfp + 1][2 * rh]     + (rh ? fb.x : fa.x);
                        float zo = acc[mf][2 * nfp + 1][2 * rh + 1] + (rh ? fb.y : fa.y);

                        float ig = fsig(zi);
                        float fg = fsig(zf);
                        float og = fsig(zo);
                        float cp = csm[rl * 16 + ul];
                        float cn = fg * cp + ig * ftanh(zj);
                        float hn = og * ftanh(cn);
                        csm[rl * 16 + ul] = cn;

                        int grow = m0 + rl;
                        ((__half*)hout)[(size_t)grow * HID + hidx] = __float2half_rn(hn);
                        if (LAST && t == SEQ - 1)
                            h_final[(size_t)grow * HID + gu] = hn;
                    }
                }
            }
        }

        // Arrive-early grid barrier (CTA-wide sync before arrive: all hin(t)
        // reads and hout stores of this CTA are complete).
        if (t < SEQ) {
            __syncthreads();
            if (tid == 0) {
                __threadfence();
                unsigned int old = atomicAdd(&g_bar_count, 1);
                if (old == NCTA - 1) {
                    g_bar_count = 0;
                    __threadfence();
                    atomicAdd(&g_bar_phase, 1);
                }
            }
        }

        // x-epilogue inside barrier window (6 STG.128 per thread).
        if (FUSE_X && t > 0) {
            uint32_t gxo[24];
            #pragma unroll
            for (int mf = 0; mf < 3; mf++) {
                #pragma unroll
                for (int nf = 0; nf < 4; nf++) {
                    int ncl = wn + nf * 8 + 2 * q;
                    float b0 = biasx[ncl], b1 = biasx[ncl + 1];
                    __half2 h0 = __floats2half2_rn(accx[mf][nf][0] + b0,
                                                   accx[mf][nf][1] + b1);
                    __half2 h1 = __floats2half2_rn(accx[mf][nf][2] + b0,
                                                   accx[mf][nf][3] + b1);
                    gxo[(mf * 4 + nf) * 2]     = *(uint32_t*)&h0;
                    gxo[(mf * 4 + nf) * 2 + 1] = *(uint32_t*)&h1;
                }
            }
            size_t base = ((((size_t)(t - 1) * 128 + blockIdx.x) * 8 + warp) * 32
                           + lane) * 24;
            #pragma unroll
            for (int j = 0; j < 6; j++)
                *(uint4*)(gx_out + base + j * 4) = *(uint4*)(gxo + j * 4);
        }

        // Prefetch next step's gx (input gx is fully materialized pre-launch).
        if (t + 1 < SEQ) {
            const uint4* gp = (const uint4*)gx +
                ((((size_t)(t + 1) * 128 + blockIdx.x) * 8 + warp) * 32 + lane) * 6;
            #pragma unroll
            for (int j = 0; j < 6; j++) *(uint4*)(gxw + j * 4) = gp[j];
        }

        // Per-warp barrier WAIT: lane0 spins on phase, warp proceeds alone.
        if (t < SEQ) {
            if (lane == 0) {
                while (ld_acq(&g_bar_phase) == phase) { }
            }
            __syncwarp();
            phase++;
        }
    }
}

// ---------------------------------------------------------------------------
// SELU + head kernels (unchanged, fp32)
// ---------------------------------------------------------------------------
__device__ __forceinline__ float selu_f(float x) {
    const float sc = 1.0507009873554805f;
    const float al = 1.6732632423543772f;
    return x > 0.f ? sc * x : sc * al * expm1f(x);
}

template <bool BIAS, bool SELU>
__global__ void __launch_bounds__(256, 2)
sgemm128(const float* __restrict__ A, const float* __restrict__ B,
         float* __restrict__ C, int M, int N, int K,
         const float* __restrict__ bias) {
    __shared__ float As[16][128];
    __shared__ float Bs[16][128];

    const int bm  = blockIdx.y * 128;
    const int bn  = blockIdx.x * 128;
    const int tid = threadIdx.x;
    const int tx  = (tid & 15) * 8;
    const int ty  = (tid >> 4) * 8;

    float acc[8][8] = {};

    const int arow = tid >> 2;
    const int acol = (tid & 3) << 2;
    const int brow = tid >> 5;
    const int bcol = (tid & 31) << 2;

    const float* Aptr = A + (size_t)(bm + arow) * K + acol;
    const float* Bptr = B + (size_t)brow * N + bn + bcol;

    for (int k0 = 0; k0 < K; k0 += 16) {
        float4 a0 = *(const float4*)(Aptr);
        float4 a1 = *(const float4*)(Aptr + (size_t)64 * K);
        float4 b0 = *(const float4*)(Bptr);
        float4 b1 = *(const float4*)(Bptr + (size_t)8 * N);

        As[acol + 0][arow]      = a0.x;
        As[acol + 1][arow]      = a0.y;
        As[acol + 2][arow]      = a0.z;
        As[acol + 3][arow]      = a0.w;
        As[acol + 0][arow + 64] = a1.x;
        As[acol + 1][arow + 64] = a1.y;
        As[acol + 2][arow + 64] = a1.z;
        As[acol + 3][arow + 64] = a1.w;
        *(float4*)&Bs[brow][bcol]     = b0;
        *(float4*)&Bs[brow + 8][bcol] = b1;
        __syncthreads();

        #pragma unroll
        for (int kk = 0; kk < 16; kk++) {
            float ar[8], br[8];
            *(float4*)(ar)     = *(const float4*)&As[kk][ty];
            *(float4*)(ar + 4) = *(const float4*)&As[kk][ty + 4];
            *(float4*)(br)     = *(const float4*)&Bs[kk][tx];
            *(float4*)(br + 4) = *(const float4*)&Bs[kk][tx + 4];
            #pragma unroll
            for (int i = 0; i < 8; i++)
                #pragma unroll
                for (int j = 0; j < 8; j++)
                    acc[i][j] += ar[i] * br[j];
        }
        __syncthreads();

        Aptr += 16;
        Bptr += (size_t)16 * N;
    }

    float bv[8];
    if (BIAS) {
        #pragma unroll
        for (int j = 0; j < 8; j++) bv[j] = bias[bn + tx + j];
    }

    #pragma unroll
    for (int i = 0; i < 8; i++) {
        float v[8];
        #pragma unroll
        for (int j = 0; j < 8; j++) {
            float x = acc[i][j];
            if (BIAS) x += bv[j];
            if (SELU) x = selu_f(x);
            v[j] = x;
        }
        float* crow = C + (size_t)(bm + ty + i) * N + bn + tx;
        *(float4*)(crow)     = *(float4*)(v);
        *(float4*)(crow + 4) = *(float4*)(v + 4);
    }
}

__global__ void bn1_kernel(const float* __restrict__ h, const float* __restrict__ gamma,
                           const float* __restrict__ beta, float* __restrict__ y) {
    int f = blockIdx.x;
    int r = threadIdx.x;
    int s = f >> 9;
    int j = f & 511;
    float v = h[((size_t)(s * BATCH + r)) * HID + j];

    __shared__ float sd[256];
    sd[r] = v; __syncthreads();
    for (int w = 128; w > 0; w >>= 1) { if (r < w) sd[r] += sd[r + w]; __syncthreads(); }
    float mu = sd[0] * (1.f / 256.f);
    __syncthreads();
    float d = v - mu;
    sd[r] = d * d; __syncthreads();
    for (int w = 128; w > 0; w >>= 1) { if (r < w) sd[r] += sd[r + w]; __syncthreads(); }
    float var = sd[0] * (1.f / 256.f);

    float sc = gamma[f] * rsqrtf(var + 1e-3f);
    y[r * 1536 + f] = d * sc + beta[f];
}

__global__ void bn_kernel(const float* __restrict__ x, const float* __restrict__ gamma,
                          const float* __restrict__ beta, float* __restrict__ y,
                          int stride) {
    int f = blockIdx.x;
    int r = threadIdx.x;
    float v = x[(size_t)r * stride + f];

    __shared__ float sd[256];
    sd[r] = v; __syncthreads();
    for (int w = 128; w > 0; w >>= 1) { if (r < w) sd[r] += sd[r + w]; __syncthreads(); }
    float mu = sd[0] * (1.f / 256.f);
    __syncthreads();
    float d = v - mu;
    sd[r] = d * d; __syncthreads();
    for (int w = 128; w > 0; w >>= 1) { if (r < w) sd[r] += sd[r + w]; __syncthreads(); }
    float var = sd[0] * (1.f / 256.f);

    float sc = gamma[f] * rsqrtf(var + 1e-3f);
    y[(size_t)r * stride + f] = d * sc + beta[f];
}

__global__ void pad_w2(const float* __restrict__ W2, const float* __restrict__ b2,
                       float* __restrict__ w2p, float* __restrict__ b2p) {
    int idx = blockIdx.x * 256 + threadIdx.x;
    int n = idx & 127;
    int k = idx >> 7;
    w2p[idx] = (n < 102) ? W2[k * 102 + n] : 0.f;
    if (idx < 128) b2p[idx] = (idx < 102) ? b2[idx] : 0.f;
}

__global__ void out_kernel(const float* __restrict__ a, const float* __restrict__ W3,
                           const float* __restrict__ b3, float* __restrict__ out) {
    int idx = blockIdx.x * 256 + threadIdx.x;
    int b = idx >> 2;
    int n = idx & 3;
    float acc = b3[n];
    #pragma unroll 6
    for (int k = 0; k < 102; k++)
        acc += a[b * 128 + k] * W3[k * 4 + n];
    out[idx] = acc;
}

// ---------------------------------------------------------------------------
// Launch
// ---------------------------------------------------------------------------
extern "C" void kernel_launch(void* const* d_in, const int* in_sizes, int n_in,
                              void* d_out, int out_size) {
    const int*   t1   = (const int*)d_in[0];
    const int*   t2   = (const int*)d_in[1];
    const int*   t3   = (const int*)d_in[2];
    const float* emb  = (const float*)d_in[3];
    const float* lw   = (const float*)d_in[4];
    const float* lb   = (const float*)d_in[5];
    const float* bn1g = (const float*)d_in[6];
    const float* bn1b = (const float*)d_in[7];
    const float* W1   = (const float*)d_in[8];
    const float* b1   = (const float*)d_in[9];
    const float* bn2g = (const float*)d_in[10];
    const float* bn2b = (const float*)d_in[11];
    const float* W2   = (const float*)d_in[12];
    const float* b2   = (const float*)d_in[13];
    const float* bn3g = (const float*)d_in[14];
    const float* bn3b = (const float*)d_in[15];
    const float* W3   = (const float*)d_in[16];
    const float* b3   = (const float*)d_in[17];
    float* out = (float*)d_out;

    uint32_t *seqH, *gxA, *gxB, *hPa, *hPb, *wx0p, *mrg, *wh2p;
    float *hf, *bp;
    float *xn1, *a1, *xn2, *w2p, *b2p, *a2, *a2n;
    cudaGetSymbolAddress((void**)&seqH, g_seqH);
    cudaGetSymbolAddress((void**)&gxA,  g_gxA);
    cudaGetSymbolAddress((void**)&gxB,  g_gxB);
    cudaGetSymbolAddress((void**)&hPa,  g_hPa);
    cudaGetSymbolAddress((void**)&hPb,  g_hPb);
    cudaGetSymbolAddress((void**)&hf,   g_hf);
    cudaGetSymbolAddress((void**)&wx0p, g_Wx0P);
    cudaGetSymbolAddress((void**)&mrg,  g_mrg);
    cudaGetSymbolAddress((void**)&wh2p, g_Wh2P);
    cudaGetSymbolAddress((void**)&bp,   g_bp);
    cudaGetSymbolAddress((void**)&xn1,  g_xn1);
    cudaGetSymbolAddress((void**)&a1,   g_a1);
    cudaGetSymbolAddress((void**)&xn2,  g_xn2);
    cudaGetSymbolAddress((void**)&w2p,  g_W2p);
    cudaGetSymbolAddress((void**)&b2p,  g_b2p);
    cudaGetSymbolAddress((void**)&a2,   g_a2);
    cudaGetSymbolAddress((void**)&a2n,  g_a2n);

    cudaFuncSetAttribute(lstm_layer<true, false>,
                         cudaFuncAttributeMaxDynamicSharedMemorySize, SMF_BYTES);
    cudaFuncSetAttribute(lstm_layer<false, true>,
                         cudaFuncAttributeMaxDynamicSharedMemorySize, SMP_BYTES);
    cudaFuncSetAttribute(gemm_x_f16,
                         cudaFuncAttributeMaxDynamicSharedMemorySize, X_BYTES);

    prep_kernel<<<(3 * 1024 * G4) / 256, 256>>>(lw, lb, wx0p, mrg, wh2p, bp);
    embed_kernel<<<BB * SEQ, 128>>>(t1, t2, t3, emb, (__half2*)seqH);

    // Layer 0: x-GEMM from embeddings; fused recurrence emits layer-1 gx.
    gemm_x_f16<<<dim3(32, (BB * SEQ) / 128), 256, X_BYTES>>>(seqH, wx0p, bp, gxA);
    lstm_layer<true, false><<<NCTA, 256, SMF_BYTES>>>(
        mrg, gxA, bp + G4, hPa, hPb, gxB, hf);

    // Layer 1: fused recurrence emits layer-2 gx.
    lstm_layer<true, false><<<NCTA, 256, SMF_BYTES>>>(
        mrg + (size_t)32 * 32768, gxB, bp + 2 * G4, hPa, hPb, gxA, hf);

    // Layer 2: plain recurrence, writes final hidden state.
    lstm_layer<false, true><<<NCTA, 256, SMP_BYTES>>>(
        wh2p, gxA, nullptr, hPa, hPb, gxB, hf);

    bn1_kernel<<<1536, 256>>>(hf, bn1g, bn1b, xn1);
    sgemm128<true, true><<<dim3(1024 / 128, BATCH / 128), 256>>>(
        xn1, W1, a1, BATCH, 1024, 1536, b1);
    bn_kernel<<<1024, 256>>>(a1, bn2g, bn2b, xn2, 1024);
    pad_w2<<<(1024 * 128) / 256, 256>>>(W2, b2, w2p, b2p);
    sgemm128<true, true><<<dim3(1, BATCH / 128), 256>>>(
        xn2, w2p, a2, BATCH, 128, 1024, b2p);
    bn_kernel<<<102, 256>>>(a2, bn3g, bn3b, a2n, 128);
    out_kernel<<<4, 256>>>(a2n, W3, b3, out);
}